// round 14
// baseline (speedup 1.0000x reference)
#include <cuda_runtime.h>
#include <cuda_fp16.h>
#include <math.h>

// ---------------------------------------------------------------------------
// Problem: B=32,T=512,N=4,E=16, NI=16,EI=8, HN=HE=128, MH=256, C=8
// HW model: __device__ statics are HOST-resident (NVLink-C2C ~230 GB/s,
// L2-bypassed, L1-cacheable). r13: LSTM is issue-count bound (fma2 = 54% of
// issue), smem/regs at capacity -> left alone. r14: classifier FLOP factoring
// (PS/PD per-node projections) inside the proven BM=64 block (grid 4096).
// ---------------------------------------------------------------------------

typedef unsigned long long u64;

#define SPB 5

// ---- scratch arena (host-resident), fp16 payloads ----
#define OFF_E4    0L
#define OFF_X4    16777216L
#define OFF_HN    20971520L
#define OFF_HE    25165824L
#define OFF_SLACK 41943040L
__device__ float g_arena[41943104];

// ---- packed fp32x2 helpers ----
__device__ __forceinline__ u64 pk2(float lo, float hi) {
    u64 r; asm("mov.b64 %0, {%1,%2};" : "=l"(r) : "f"(lo), "f"(hi)); return r;
}
__device__ __forceinline__ void up2(float& lo, float& hi, u64 v) {
    asm("mov.b64 {%0,%1}, %2;" : "=f"(lo), "=f"(hi) : "l"(v));
}
__device__ __forceinline__ void fma2(u64& c, u64 a, u64 b) {
    asm("fma.rn.f32x2 %0, %1, %2, %0;" : "+l"(c) : "l"(a), "l"(b));
}
__device__ __forceinline__ u64 h2f2(unsigned h) {
    float2 f = __half22float2(*(const __half2*)&h);
    return pk2(f.x, f.y);
}

// ---- MUFU-free exp (FMA pipe), err ~1e-7 for |x|<=~40 ----
__device__ __forceinline__ float pexp(float x) {
    float t = x * 1.44269504088896f;
    float k = t + 12582912.0f;
    int   e = __float_as_int(k) - 0x4B400000;
    float n = k - 12582912.0f;
    float f = t - n;
    float p =              1.54035304e-4f;
    p = fmaf(p, f, 1.33335581e-3f);
    p = fmaf(p, f, 9.61812911e-3f);
    p = fmaf(p, f, 5.55041087e-2f);
    p = fmaf(p, f, 2.40226507e-1f);
    p = fmaf(p, f, 6.93147181e-1f);
    p = fmaf(p, f, 1.0f);
    float s = __int_as_float((e + 127) << 23);
    return p * s;
}
__device__ __forceinline__ float rcpa(float x) {
    float r; asm("rcp.approx.f32 %0, %1;" : "=f"(r) : "f"(x)); return r;
}
__device__ __forceinline__ float clamp15(float x) {
    return fminf(fmaxf(x, -15.f), 15.f);
}

// ---------------------------------------------------------------------------
// SMEM microtile GEMM (FF path): at[k*132+r], w[k*128+c]
// ---------------------------------------------------------------------------
__device__ __forceinline__ void smem_gemm(
    const float* at, const float* w, int K, int tx, int ty, u64 acc[4][8])
{
#pragma unroll
    for (int i = 0; i < 4; i++)
#pragma unroll
        for (int j = 0; j < 8; j++) acc[i][j] = 0ull;
#pragma unroll 8
    for (int k = 0; k < K; k++) {
        ulonglong2 aa = *(const ulonglong2*)&at[k * 132 + ty];
        ulonglong2 ab = *(const ulonglong2*)&at[k * 132 + ty + 4];
        float4 c0 = *(const float4*)&w[k * 128 + tx];
        float4 c1 = *(const float4*)&w[k * 128 + tx + 4];
        u64 bd[8];
        bd[0] = pk2(c0.x, c0.x); bd[1] = pk2(c0.y, c0.y);
        bd[2] = pk2(c0.z, c0.z); bd[3] = pk2(c0.w, c0.w);
        bd[4] = pk2(c1.x, c1.x); bd[5] = pk2(c1.y, c1.y);
        bd[6] = pk2(c1.z, c1.z); bd[7] = pk2(c1.w, c1.w);
        u64 ap[4] = { aa.x, aa.y, ab.x, ab.y };
#pragma unroll
        for (int i = 0; i < 4; i++)
#pragma unroll
            for (int j = 0; j < 8; j++)
                fma2(acc[i][j], ap[i], bd[j]);
    }
}

__device__ __forceinline__ void unpack_epi(
    u64 acc[4][8], const float* bias, int tx, int MIX, float v[8][8])
{
#pragma unroll
    for (int i = 0; i < 4; i++)
#pragma unroll
        for (int j = 0; j < 8; j++)
            up2(v[2 * i][j], v[2 * i + 1][j], acc[i][j]);
    float bv[8];
    *(float4*)&bv[0] = *(const float4*)&bias[tx];
    *(float4*)&bv[4] = *(const float4*)&bias[tx + 4];
    if (MIX) {
#pragma unroll
        for (int g = 0; g < 2; g++) {
            float s[8];
#pragma unroll
            for (int j = 0; j < 8; j++)
                s[j] = v[4*g][j] + v[4*g+1][j] + v[4*g+2][j] + v[4*g+3][j];
#pragma unroll
            for (int r = 0; r < 4; r++)
#pragma unroll
                for (int j = 0; j < 8; j++)
                    v[4*g+r][j] = fmaxf((s[j] + v[4*g+r][j]) * 0.2f + bv[j], 0.f);
        }
    } else {
#pragma unroll
        for (int r = 0; r < 8; r++)
#pragma unroll
            for (int j = 0; j < 8; j++)
                v[r][j] = fmaxf(v[r][j] + bv[j], 0.f);
    }
}

__device__ __forceinline__ void store_at_T(float* at, float v[8][8], int tx, int ty)
{
#pragma unroll
    for (int j = 0; j < 8; j++) {
        float* q = at + (tx + j) * 132 + ty;
        *(float4*)(q)     = make_float4(v[0][j], v[1][j], v[2][j], v[3][j]);
        *(float4*)(q + 4) = make_float4(v[4][j], v[5][j], v[6][j], v[7][j]);
    }
}

// ---------------------------------------------------------------------------
// FF path: in -> L1..L4 (MIX34: graph-conv mixes) -> out fp16 [row][128].
// ---------------------------------------------------------------------------
template <int K1, int MIX34>
__global__ __launch_bounds__(256) void fused_ff(
    const float* __restrict__ in,
    const float* __restrict__ W1, const float* __restrict__ b1,
    const float* __restrict__ W2, const float* __restrict__ b2,
    const float* __restrict__ W3, const float* __restrict__ b3,
    const float* __restrict__ W4, const float* __restrict__ b4,
    __half* __restrict__ out)
{
    extern __shared__ float s[];
    float* wa = s;
    float* wb = wa + 128 * 128;
    float* at = wb + 128 * 128;
    const int tid = threadIdx.x;
    const long bm = (long)blockIdx.x * 128;
    const int tx = (tid & 15) * 8;
    const int ty = (tid >> 4) * 8;

    for (int i = tid; i < K1 * 32; i += 256)
        ((float4*)wa)[i] = ((const float4*)W1)[i];
    for (int i = tid; i < 4096; i += 256)
        ((float4*)wb)[i] = ((const float4*)W2)[i];
    {
        const int r = tid >> 1;
        const int h = tid & 1;
        const int C = K1 / 2;
        const float* p = in + (bm + r) * K1 + h * C;
#pragma unroll
        for (int c = 0; c < C; c += 4) {
            float4 vv = *(const float4*)(p + c);
            at[(h * C + c + 0) * 132 + r] = vv.x;
            at[(h * C + c + 1) * 132 + r] = vv.y;
            at[(h * C + c + 2) * 132 + r] = vv.z;
            at[(h * C + c + 3) * 132 + r] = vv.w;
        }
    }
    __syncthreads();

    u64 acc[4][8];
    float v[8][8];

    smem_gemm(at, wa, K1, tx, ty, acc);
    __syncthreads();
    unpack_epi(acc, b1, tx, 0, v);
    store_at_T(at, v, tx, ty);
    for (int i = tid; i < 4096; i += 256)
        ((float4*)wa)[i] = ((const float4*)W3)[i];
    __syncthreads();

    smem_gemm(at, wb, 128, tx, ty, acc);
    __syncthreads();
    unpack_epi(acc, b2, tx, 0, v);
    store_at_T(at, v, tx, ty);
    for (int i = tid; i < 4096; i += 256)
        ((float4*)wb)[i] = ((const float4*)W4)[i];
    __syncthreads();

    smem_gemm(at, wa, 128, tx, ty, acc);
    __syncthreads();
    unpack_epi(acc, b3, tx, MIX34, v);
    store_at_T(at, v, tx, ty);
    __syncthreads();

    smem_gemm(at, wb, 128, tx, ty, acc);
    unpack_epi(acc, b4, tx, MIX34, v);
#pragma unroll
    for (int r = 0; r < 8; r++) {
        __half2 h4[4];
#pragma unroll
        for (int j2 = 0; j2 < 4; j2++)
            h4[j2] = __floats2half2_rn(v[r][2*j2], v[r][2*j2+1]);
        __half* q = out + (bm + ty + r) * 128 + tx;
        *(uint4*)q = *(uint4*)h4;
    }
}

// ---------------------------------------------------------------------------
// LSTM v7 (r13, passing — unchanged): 512 threads, K-SPLIT.
// ---------------------------------------------------------------------------
#define LSTM7_SMEM_BYTES (49152 * 4 + (640 * 3 + 5120) * 4)   // 224768 B

__global__ __launch_bounds__(512, 1) void lstm7(
    const __half* __restrict__ x_n, const float* __restrict__ Wih_n,
    const float* __restrict__ Whh_n, const float* __restrict__ b_n, __half* __restrict__ hn,
    const __half* __restrict__ x_e, const float* __restrict__ Wih_e,
    const float* __restrict__ Whh_e, const float* __restrict__ b_e, __half* __restrict__ he)
{
    extern __shared__ float sm[];
    unsigned* wsm = (unsigned*)sm;            // [kh*24576 + k2s*512 + col], k2s 0..47
    float* hsm = (float*)(wsm + 49152);       // [i*128 + k]
    float* xsm = hsm + 640;                   // [i*128 + k]
    float* csm = xsm + 640;                   // [i*128 + k]
    float* zsm = csm + 640;                   // [kh*2560 + i*512 + c]

    const int tid = threadIdx.x;
    const int col = tid & 255;
    const int kh  = tid >> 8;                 // 0: Whh half, 1: Wih half
    const int c2  = 2 * col;

    const float* Wih; const float* Whh; const float* bias;
    const __half* x; __half* out;
    int seq0, nseq, is_node;

    if (blockIdx.x < 26) {
        Wih = Wih_n; Whh = Whh_n; bias = b_n; x = x_n; out = hn;
        seq0 = blockIdx.x * SPB; nseq = 128; is_node = 1;
    } else {
        Wih = Wih_e; Whh = Whh_e; bias = b_e; x = x_e; out = he;
        seq0 = (blockIdx.x - 26) * SPB; nseq = 512; is_node = 0;
    }
    const long xstep = is_node ? (4 * 128) : (16 * 128);   // halves per t

    for (int idx = tid; idx < 49152; idx += 512) {
        int khi = idx / 24576;
        int rem = idx - khi * 24576;
        int k2s = rem >> 9, c = rem & 511;
        const float* Wsrc = khi ? Wih : Whh;
        __half2 hh = __floats2half2_rn(Wsrc[(size_t)(32 + 2 * k2s) * 512 + c],
                                       Wsrc[(size_t)(33 + 2 * k2s) * 512 + c]);
        wsm[idx] = *(unsigned*)&hh;
    }
    u64 wreg[32];
    {
        const float* Wmy = kh ? Wih : Whh;
#pragma unroll
        for (int k2 = 0; k2 < 16; k2++) {
            float2 la = *(const float2*)&Wmy[(size_t)(2 * k2) * 512 + c2];
            float2 lb = *(const float2*)&Wmy[(size_t)(2 * k2 + 1) * 512 + c2];
            wreg[2 * k2]     = pk2(la.x, lb.x);
            wreg[2 * k2 + 1] = pk2(la.y, lb.y);
        }
    }

    for (int idx = tid; idx < 640; idx += 512) {
        hsm[idx] = 0.f; xsm[idx] = 0.f; csm[idx] = 0.f;
    }

    const int i_a = tid >> 6;                 // 0..7; active if <5
    const int kk  = tid & 63;
    const int act = (i_a < 5);
    int sqa = seq0 + i_a;
    const int va = act && (sqa < nseq);
    long rowa = 0;
    if (act)
        rowa = is_node ? ((long)(sqa >> 2) * 2048 + (sqa & 3))
                       : ((long)(sqa >> 4) * 8192 + (sqa & 15));
    const __half* pa = x + rowa * 128 + 2 * kk;
    {
        unsigned ra = va ? *(const unsigned*)pa : 0u;
        if (act) {
            float2 f = __half22float2(*(const __half2*)&ra);
            *(float2*)&xsm[i_a * 128 + 2 * kk] = f;
        }
    }
    const float* obase = kh ? xsm : hsm;
    float* zpart = zsm + kh * 2560;
    __syncthreads();

    for (int t = 0; t < 512; t++) {
        int tn = (t + 1 < 512) ? (t + 1) : t;
        unsigned xra = va ? *(const unsigned*)(pa + (long)tn * xstep) : 0u;

        u64 aA0 = 0, aA1 = 0, aA2 = 0, aA3 = 0, aA4 = 0;
        u64 aB0 = 0, aB1 = 0, aB2 = 0, aB3 = 0, aB4 = 0;

#pragma unroll
        for (int k2 = 0; k2 < 16; k2 += 2) {
            ulonglong2 h0 = *(const ulonglong2*)&obase[0 * 128 + 2 * k2];
            ulonglong2 h1 = *(const ulonglong2*)&obase[1 * 128 + 2 * k2];
            ulonglong2 h2 = *(const ulonglong2*)&obase[2 * 128 + 2 * k2];
            ulonglong2 h3 = *(const ulonglong2*)&obase[3 * 128 + 2 * k2];
            ulonglong2 h4 = *(const ulonglong2*)&obase[4 * 128 + 2 * k2];
            u64 wA0 = wreg[2 * k2],     wB0 = wreg[2 * k2 + 1];
            u64 wA1 = wreg[2 * k2 + 2], wB1 = wreg[2 * k2 + 3];
            fma2(aA0, h0.x, wA0); fma2(aA0, h0.y, wA1);
            fma2(aB0, h0.x, wB0); fma2(aB0, h0.y, wB1);
            fma2(aA1, h1.x, wA0); fma2(aA1, h1.y, wA1);
            fma2(aB1, h1.x, wB0); fma2(aB1, h1.y, wB1);
            fma2(aA2, h2.x, wA0); fma2(aA2, h2.y, wA1);
            fma2(aB2, h2.x, wB0); fma2(aB2, h2.y, wB1);
            fma2(aA3, h3.x, wA0); fma2(aA3, h3.y, wA1);
            fma2(aB3, h3.x, wB0); fma2(aB3, h3.y, wB1);
            fma2(aA4, h4.x, wA0); fma2(aA4, h4.y, wA1);
            fma2(aB4, h4.x, wB0); fma2(aB4, h4.y, wB1);
        }
        const unsigned* wbase = wsm + kh * 24576;
#pragma unroll 4
        for (int q = 0; q < 48; q += 2) {
            uint2 wa_ = *(const uint2*)&wbase[q * 512 + c2];
            uint2 wb_ = *(const uint2*)&wbase[(q + 1) * 512 + c2];
            u64 wA0 = h2f2(wa_.x), wB0 = h2f2(wa_.y);
            u64 wA1 = h2f2(wb_.x), wB1 = h2f2(wb_.y);
            int ko = 32 + 2 * q;
            ulonglong2 h0 = *(const ulonglong2*)&obase[0 * 128 + ko];
            ulonglong2 h1 = *(const ulonglong2*)&obase[1 * 128 + ko];
            ulonglong2 h2 = *(const ulonglong2*)&obase[2 * 128 + ko];
            ulonglong2 h3 = *(const ulonglong2*)&obase[3 * 128 + ko];
            ulonglong2 h4 = *(const ulonglong2*)&obase[4 * 128 + ko];
            fma2(aA0, h0.x, wA0); fma2(aA0, h0.y, wA1);
            fma2(aB0, h0.x, wB0); fma2(aB0, h0.y, wB1);
            fma2(aA1, h1.x, wA0); fma2(aA1, h1.y, wA1);
            fma2(aB1, h1.x, wB0); fma2(aB1, h1.y, wB1);
            fma2(aA2, h2.x, wA0); fma2(aA2, h2.y, wA1);
            fma2(aB2, h2.x, wB0); fma2(aB2, h2.y, wB1);
            fma2(aA3, h3.x, wA0); fma2(aA3, h3.y, wA1);
            fma2(aB3, h3.x, wB0); fma2(aB3, h3.y, wB1);
            fma2(aA4, h4.x, wA0); fma2(aA4, h4.y, wA1);
            fma2(aB4, h4.x, wB0); fma2(aB4, h4.y, wB1);
        }

        {
            float l, h, zA, zB;
            up2(l, h, aA0); zA = l + h; up2(l, h, aB0); zB = l + h;
            *(float2*)&zpart[0 * 512 + c2] = make_float2(zA, zB);
            up2(l, h, aA1); zA = l + h; up2(l, h, aB1); zB = l + h;
            *(float2*)&zpart[1 * 512 + c2] = make_float2(zA, zB);
            up2(l, h, aA2); zA = l + h; up2(l, h, aB2); zB = l + h;
            *(float2*)&zpart[2 * 512 + c2] = make_float2(zA, zB);
            up2(l, h, aA3); zA = l + h; up2(l, h, aB3); zB = l + h;
            *(float2*)&zpart[3 * 512 + c2] = make_float2(zA, zB);
            up2(l, h, aA4); zA = l + h; up2(l, h, aB4); zB = l + h;
            *(float2*)&zpart[4 * 512 + c2] = make_float2(zA, zB);
        }
        __syncthreads();

        if (act) {
            float2 f = __half22float2(*(const __half2*)&xra);
            *(float2*)&xsm[i_a * 128 + 2 * kk] = f;
        }
#pragma unroll 1
        for (int q = tid; q < SPB * 128; q += 512) {
            int i = q >> 7, hh_ = q & 127;
            const float* z0 = zsm + i * 512;
            const float* z1 = zsm + 2560 + i * 512;
            float zi = clamp15(z0[hh_]       + z1[hh_]       + bias[hh_]);
            float zf = clamp15(z0[128 + hh_] + z1[128 + hh_] + bias[128 + hh_]);
            float zg = clamp15(z0[256 + hh_] + z1[256 + hh_] + bias[256 + hh_]);
            float zo = clamp15(z0[384 + hh_] + z1[384 + hh_] + bias[384 + hh_]);
            float ei = pexp(-zi);
            float ef = pexp(-zf);
            float g2 = pexp(2.0f * zg);
            float eo = pexp(-zo);
            float pi_ = 1.f + ei, pf_ = 1.f + ef, pg_ = g2 + 1.f;
            float cold = csm[q];
            float num = cold * pi_ * pg_ + (g2 - 1.f) * pf_;
            float cn  = num * rcpa(pf_ * pi_ * pg_);
            float cc  = clamp15(cn);
            float T   = pexp(2.0f * cc);
            float hv  = (T - 1.f) * rcpa((T + 1.f) * (1.f + eo));
            csm[q] = cn;
            hsm[q] = hv;
            int sq = seq0 + i;
            if (sq < nseq) {
                long row = is_node ? ((long)(sq >> 2) * 2048 + (sq & 3))
                                   : ((long)(sq >> 4) * 8192 + (sq & 15));
                out[row * 128 + (long)t * xstep + hh_] = __float2half(hv);
            }
        }
        __syncthreads();
    }
}

// ---------------------------------------------------------------------------
// Classifier v3 (FACTORED, BM=64, grid 4096):
//   Phase A: PS = hn16 @ Wc1[0:128], PD = hn16 @ Wc1[128:256]  (per node)
//   Phase B: acc = he64 @ Wc1[256:384]; epi: + PS[src] + PD[dst] + bc1, relu
//   Phase C: ct @ Wc2 + bc2
// Per-thread fma2: 12.3K -> 6.1K vs r7 version. Same Wc1 streaming & grid.
// ---------------------------------------------------------------------------
#define C1F3_SMEM_FLOATS (2048 + 1088 + 4096 + 4096 + 4096 + 17408 + 2048)

__global__ __launch_bounds__(256) void c1final3(
    const __half* __restrict__ hn, const __half* __restrict__ he,
    const float* __restrict__ Wc1, const float* __restrict__ bc1,
    const float* __restrict__ Wc2, const float* __restrict__ bc2,
    float* __restrict__ out)
{
    extern __shared__ float s[];
    float* hn_t = s;               // [k*16 + r], 16 node rows transposed, k 0..127
    float* As   = hn_t + 2048;     // [k*68 + r], 16 x 64 he tile (pad 68)
    float* Bs   = As + 1088;       // [k*256 + c], 16 x 256 Wc1 tile
    float* PS   = Bs + 4096;       // [r*256 + c], 16 x 256 src projections
    float* PD   = PS + 4096;       // 16 x 256 dst projections
    float* ct   = PD + 4096;       // [c*68 + r], 256 x 64 (pad 68)
    float* wc2  = ct + 17408;      // 256 x 8
    const int tid = threadIdx.x;
    const long bm = (long)blockIdx.x * 64;
    const long bt0 = bm >> 4;

    for (int i = tid; i < 512; i += 256)
        ((float4*)wc2)[i] = ((const float4*)Wc2)[i];

    // stage hn_t[k*16 + r] = hn[(bt0*4 + r)*128 + k]  (16 node rows, fp16->f32)
    for (int idx = tid; idx < 2048; idx += 256) {
        int k = idx >> 4, r = idx & 15;
        hn_t[idx] = __half2float(hn[(bt0 * 4 + r) * 128 + k]);
    }
    __syncthreads();

    const int brow = tid >> 4;            // 0..15
    const int bcol = (tid & 15) * 16;

    // ---- Phase A: PS (pass 0), PD (pass 1); 2 rows x 8 cols per thread ----
    {
        const int rA = (tid >> 5) * 2;    // 0,2,..,14
        const int cA = (tid & 31) * 8;    // 0..248
#pragma unroll 1
        for (int pass = 0; pass < 2; pass++) {
            u64 pacc[2][4];
#pragma unroll
            for (int r = 0; r < 2; r++)
#pragma unroll
                for (int j = 0; j < 4; j++) pacc[r][j] = 0ull;

            for (int k0 = 0; k0 < 128; k0 += 16) {
                const float* bp = Wc1 + (size_t)(pass * 128 + k0 + brow) * 256 + bcol;
                float4 bv0 = *(const float4*)(bp);
                float4 bv1 = *(const float4*)(bp + 4);
                float4 bv2 = *(const float4*)(bp + 8);
                float4 bv3 = *(const float4*)(bp + 12);
                float* bq = Bs + brow * 256 + bcol;
                *(float4*)(bq)      = bv0;
                *(float4*)(bq + 4)  = bv1;
                *(float4*)(bq + 8)  = bv2;
                *(float4*)(bq + 12) = bv3;
                __syncthreads();
#pragma unroll
                for (int kkk = 0; kkk < 16; kkk++) {
                    float a0 = hn_t[(k0 + kkk) * 16 + rA];
                    float a1 = hn_t[(k0 + kkk) * 16 + rA + 1];
                    u64 d0 = pk2(a0, a0);
                    u64 d1 = pk2(a1, a1);
                    ulonglong2 bb0 = *(const ulonglong2*)&Bs[kkk * 256 + cA];
                    ulonglong2 bb1 = *(const ulonglong2*)&Bs[kkk * 256 + cA + 4];
                    fma2(pacc[0][0], bb0.x, d0); fma2(pacc[0][1], bb0.y, d0);
                    fma2(pacc[0][2], bb1.x, d0); fma2(pacc[0][3], bb1.y, d0);
                    fma2(pacc[1][0], bb0.x, d1); fma2(pacc[1][1], bb0.y, d1);
                    fma2(pacc[1][2], bb1.x, d1); fma2(pacc[1][3], bb1.y, d1);
                }
                __syncthreads();
            }
            float* P = pass ? PD : PS;
#pragma unroll
            for (int r = 0; r < 2; r++) {
                float o[8];
                up2(o[0], o[1], pacc[r][0]); up2(o[2], o[3], pacc[r][1]);
                up2(o[4], o[5], pacc[r][2]); up2(o[6], o[7], pacc[r][3]);
                *(float4*)&P[(rA + r) * 256 + cA]     = make_float4(o[0], o[1], o[2], o[3]);
                *(float4*)&P[(rA + r) * 256 + cA + 4] = make_float4(o[4], o[5], o[6], o[7]);
            }
        }
    }

    // ---- Phase B: he64 @ Wc1[256:384] ----
    const int tx = (tid & 31) * 8;        // 0..248
    const int ty = (tid >> 5) * 8;        // 0..56
    const int arow = tid >> 2;            // 0..63
    const int acol = (tid & 3) * 4;

    u64 acc[4][8];
#pragma unroll
    for (int i = 0; i < 4; i++)
#pragma unroll
        for (int j = 0; j < 8; j++) acc[i][j] = 0ull;

    for (int k0 = 0; k0 < 128; k0 += 16) {
        {   // stage he tile transposed
            const __half* p = he + (bm + arow) * 128 + k0 + acol;
            uint2 raw = *(const uint2*)p;
            float2 f01 = __half22float2(*(const __half2*)&raw.x);
            float2 f23 = __half22float2(*(const __half2*)&raw.y);
            As[(acol + 0) * 68 + arow] = f01.x;
            As[(acol + 1) * 68 + arow] = f01.y;
            As[(acol + 2) * 68 + arow] = f23.x;
            As[(acol + 3) * 68 + arow] = f23.y;
        }
        const float* bp = Wc1 + (size_t)(256 + k0 + brow) * 256 + bcol;
        float4 bv0 = *(const float4*)(bp);
        float4 bv1 = *(const float4*)(bp + 4);
        float4 bv2 = *(const float4*)(bp + 8);
        float4 bv3 = *(const float4*)(bp + 12);
        float* bq = Bs + brow * 256 + bcol;
        *(float4*)(bq)      = bv0;
        *(float4*)(bq + 4)  = bv1;
        *(float4*)(bq + 8)  = bv2;
        *(float4*)(bq + 12) = bv3;
        __syncthreads();

#pragma unroll
        for (int kk = 0; kk < 16; kk++) {
            ulonglong2 aa = *(const ulonglong2*)&As[kk * 68 + ty];
            ulonglong2 ab = *(const ulonglong2*)&As[kk * 68 + ty + 4];
            float4 c0 = *(const float4*)&Bs[kk * 256 + tx];
            float4 c1 = *(const float4*)&Bs[kk * 256 + tx + 4];
            u64 bd[8];
            bd[0] = pk2(c0.x, c0.x); bd[1] = pk2(c0.y, c0.y);
            bd[2] = pk2(c0.z, c0.z); bd[3] = pk2(c0.w, c0.w);
            bd[4] = pk2(c1.x, c1.x); bd[5] = pk2(c1.y, c1.y);
            bd[6] = pk2(c1.z, c1.z); bd[7] = pk2(c1.w, c1.w);
            u64 ap[4] = { aa.x, aa.y, ab.x, ab.y };
#pragma unroll
            for (int i = 0; i < 4; i++)
#pragma unroll
                for (int j = 0; j < 8; j++)
                    fma2(acc[i][j], ap[i], bd[j]);
        }
        __syncthreads();
    }

    // epilogue: + PS[src] + PD[dst] + bc1, relu, store ct transposed
    {
        float v[8][8];
#pragma unroll
        for (int i = 0; i < 4; i++)
#pragma unroll
            for (int j = 0; j < 8; j++)
                up2(v[2 * i][j], v[2 * i + 1][j], acc[i][j]);
        float bv[8];
        *(float4*)&bv[0] = *(const float4*)&bc1[tx];
        *(float4*)&bv[4] = *(const float4*)&bc1[tx + 4];
#pragma unroll
        for (int r = 0; r < 8; r++) {
            int lr = ty + r;
            int g = lr >> 4, e = lr & 15;
            const float* ps = PS + (g * 4 + (e >> 2)) * 256 + tx;
            const float* pd = PD + (g * 4 + (e & 3)) * 256 + tx;
            float4 p0 = *(const float4*)(ps);
            float4 p1 = *(const float4*)(ps + 4);
            float4 q0 = *(const float4*)(pd);
            float4 q1 = *(const float4*)(pd + 4);
            float pa[8] = { p0.x + q0.x, p0.y + q0.y, p0.z + q0.z, p0.w + q0.w,
                            p1.x + q1.x, p1.y + q1.y, p1.z + q1.z, p1.w + q1.w };
#pragma unroll
            for (int j = 0; j < 8; j++)
                v[r][j] = fmaxf(v[r][j] + pa[j] + bv[j], 0.f);
        }
#pragma unroll
        for (int j = 0; j < 8; j++) {
            float* q = ct + (tx + j) * 68 + ty;
            *(float4*)(q)     = make_float4(v[0][j], v[1][j], v[2][j], v[3][j]);
            *(float4*)(q + 4) = make_float4(v[4][j], v[5][j], v[6][j], v[7][j]);
        }
    }
    __syncthreads();

    // ---- Phase C: ct @ Wc2 + bc2 ----
    {
        const int r = tid >> 2;
        const int c = (tid & 3) * 2;
        float f0 = bc2[c], f1 = bc2[c + 1];
#pragma unroll 8
        for (int k = 0; k < 256; k++) {
            float a = ct[k * 68 + r];
            f0 += a * wc2[k * 8 + c];
            f1 += a * wc2[k * 8 + c + 1];
        }
        float* q = out + (bm + r) * 8 + c;
        q[0] = f0; q[1] = f1;
    }
}

// ---------------------------------------------------------------------------
// Launch: FF-edge(0), FF-node(1), LSTM(2), classifier(3 = profiled slot).
// ---------------------------------------------------------------------------
extern "C" void kernel_launch(void* const* d_in, const int* in_sizes, int n_in,
                              void* d_out, int out_size)
{
    const float* x_seq = (const float*)d_in[0];
    const float* ea    = (const float*)d_in[1];
    const float* Wn1   = (const float*)d_in[2];
    const float* bn1   = (const float*)d_in[3];
    const float* Wn2   = (const float*)d_in[4];
    const float* bn2   = (const float*)d_in[5];
    const float* We1   = (const float*)d_in[6];
    const float* be1   = (const float*)d_in[7];
    const float* We2   = (const float*)d_in[8];
    const float* be2   = (const float*)d_in[9];
    const float* Wg1   = (const float*)d_in[10];
    const float* bg1   = (const float*)d_in[11];
    const float* Wg2   = (const float*)d_in[12];
    const float* bg2   = (const float*)d_in[13];
    const float* Wef1  = (const float*)d_in[14];
    const float* bef1  = (const float*)d_in[15];
    const float* Wef2  = (const float*)d_in[16];
    const float* bef2  = (const float*)d_in[17];
    const float* Wih_n = (const float*)d_in[18];
    const float* Whh_n = (const float*)d_in[19];
    const float* b_n   = (const float*)d_in[20];
    const float* Wih_e = (const float*)d_in[21];
    const float* Whh_e = (const float*)d_in[22];
    const float* b_e   = (const float*)d_in[23];
    const float* Wc1   = (const float*)d_in[24];
    const float* bc1   = (const float*)d_in[25];
    const float* Wc2   = (const float*)d_in[26];
    const float* bc2   = (const float*)d_in[27];
    float* out = (float*)d_out;

    (void)in_sizes; (void)n_in; (void)out_size;

    const int SMF   = (128 * 128 * 2 + 128 * 132) * 4;
    const int SMC3  = C1F3_SMEM_FLOATS * 4;
    cudaFuncSetAttribute(fused_ff<8, 0>,  cudaFuncAttributeMaxDynamicSharedMemorySize, SMF);
    cudaFuncSetAttribute(fused_ff<16, 1>, cudaFuncAttributeMaxDynamicSharedMemorySize, SMF);
    cudaFuncSetAttribute(lstm7,    cudaFuncAttributeMaxDynamicSharedMemorySize, LSTM7_SMEM_BYTES);
    cudaFuncSetAttribute(c1final3, cudaFuncAttributeMaxDynamicSharedMemorySize, SMC3);

    __half* e4 = (__half*)(g_arena + OFF_E4);
    __half* x4 = (__half*)(g_arena + OFF_X4);
    __half* hn = (__half*)(g_arena + OFF_HN);
    __half* he = (__half*)(g_arena + OFF_HE);

    // idx0: edge FF path ea -> e4 (fp16)
    fused_ff<8, 0><<<2048, 256, SMF>>>(ea,
        We1, be1, We2, be2, Wef1, bef1, Wef2, bef2, e4);
    // idx1: node FF path x_seq -> x4 (fp16, graph-conv mixes fused)
    fused_ff<16, 1><<<512, 256, SMF>>>(x_seq,
        Wn1, bn1, Wn2, bn2, Wg1, bg1, Wg2, bg2, x4);
    // idx2: fused LSTM v7 (512 threads, K-split)
    lstm7<<<129, 512, LSTM7_SMEM_BYTES>>>(x4, Wih_n, Whh_n, b_n, hn,
                                          e4, Wih_e, Whh_e, b_e, he);
    // idx3: classifier v3 (factored, BM=64) [profiled]
    c1final3<<<4096, 256, SMC3>>>(hn, he, Wc1, bc1, Wc2, bc2, out);
}

// round 15
// speedup vs baseline: 1.0233x; 1.0233x over previous
#include <cuda_runtime.h>
#include <cuda_fp16.h>
#include <math.h>

// ---------------------------------------------------------------------------
// Problem: B=32,T=512,N=4,E=16, NI=16,EI=8, HN=HE=128, MH=256, C=8
// HW model: __device__ statics are HOST-resident (NVLink-C2C ~230 GB/s).
// r14 lesson (twice confirmed): classifier is latency-bound; occupancy >
// FLOPs. r15: warp-specialized LSTM — Wih half runs one step ahead, off the
// recurrent critical path; one full barrier/step.
// ---------------------------------------------------------------------------

typedef unsigned long long u64;

#define SPB 5

// ---- scratch arena (host-resident), fp16 payloads ----
#define OFF_E4    0L
#define OFF_X4    16777216L
#define OFF_HN    20971520L
#define OFF_HE    25165824L
#define OFF_SLACK 41943040L
__device__ float g_arena[41943104];

// ---- packed fp32x2 helpers ----
__device__ __forceinline__ u64 pk2(float lo, float hi) {
    u64 r; asm("mov.b64 %0, {%1,%2};" : "=l"(r) : "f"(lo), "f"(hi)); return r;
}
__device__ __forceinline__ void up2(float& lo, float& hi, u64 v) {
    asm("mov.b64 {%0,%1}, %2;" : "=f"(lo), "=f"(hi) : "l"(v));
}
__device__ __forceinline__ void fma2(u64& c, u64 a, u64 b) {
    asm("fma.rn.f32x2 %0, %1, %2, %0;" : "+l"(c) : "l"(a), "l"(b));
}
__device__ __forceinline__ u64 h2f2(unsigned h) {
    float2 f = __half22float2(*(const __half2*)&h);
    return pk2(f.x, f.y);
}

// ---- MUFU-free exp (FMA pipe), err ~1e-7 for |x|<=~40 ----
__device__ __forceinline__ float pexp(float x) {
    float t = x * 1.44269504088896f;
    float k = t + 12582912.0f;
    int   e = __float_as_int(k) - 0x4B400000;
    float n = k - 12582912.0f;
    float f = t - n;
    float p =              1.54035304e-4f;
    p = fmaf(p, f, 1.33335581e-3f);
    p = fmaf(p, f, 9.61812911e-3f);
    p = fmaf(p, f, 5.55041087e-2f);
    p = fmaf(p, f, 2.40226507e-1f);
    p = fmaf(p, f, 6.93147181e-1f);
    p = fmaf(p, f, 1.0f);
    float s = __int_as_float((e + 127) << 23);
    return p * s;
}
__device__ __forceinline__ float rcpa(float x) {
    float r; asm("rcp.approx.f32 %0, %1;" : "=f"(r) : "f"(x)); return r;
}
__device__ __forceinline__ float clamp15(float x) {
    return fminf(fmaxf(x, -15.f), 15.f);
}

// ---------------------------------------------------------------------------
// SMEM microtile GEMM (FF path): at[k*132+r], w[k*128+c]
// ---------------------------------------------------------------------------
__device__ __forceinline__ void smem_gemm(
    const float* at, const float* w, int K, int tx, int ty, u64 acc[4][8])
{
#pragma unroll
    for (int i = 0; i < 4; i++)
#pragma unroll
        for (int j = 0; j < 8; j++) acc[i][j] = 0ull;
#pragma unroll 8
    for (int k = 0; k < K; k++) {
        ulonglong2 aa = *(const ulonglong2*)&at[k * 132 + ty];
        ulonglong2 ab = *(const ulonglong2*)&at[k * 132 + ty + 4];
        float4 c0 = *(const float4*)&w[k * 128 + tx];
        float4 c1 = *(const float4*)&w[k * 128 + tx + 4];
        u64 bd[8];
        bd[0] = pk2(c0.x, c0.x); bd[1] = pk2(c0.y, c0.y);
        bd[2] = pk2(c0.z, c0.z); bd[3] = pk2(c0.w, c0.w);
        bd[4] = pk2(c1.x, c1.x); bd[5] = pk2(c1.y, c1.y);
        bd[6] = pk2(c1.z, c1.z); bd[7] = pk2(c1.w, c1.w);
        u64 ap[4] = { aa.x, aa.y, ab.x, ab.y };
#pragma unroll
        for (int i = 0; i < 4; i++)
#pragma unroll
            for (int j = 0; j < 8; j++)
                fma2(acc[i][j], ap[i], bd[j]);
    }
}

__device__ __forceinline__ void unpack_epi(
    u64 acc[4][8], const float* bias, int tx, int MIX, float v[8][8])
{
#pragma unroll
    for (int i = 0; i < 4; i++)
#pragma unroll
        for (int j = 0; j < 8; j++)
            up2(v[2 * i][j], v[2 * i + 1][j], acc[i][j]);
    float bv[8];
    *(float4*)&bv[0] = *(const float4*)&bias[tx];
    *(float4*)&bv[4] = *(const float4*)&bias[tx + 4];
    if (MIX) {
#pragma unroll
        for (int g = 0; g < 2; g++) {
            float s[8];
#pragma unroll
            for (int j = 0; j < 8; j++)
                s[j] = v[4*g][j] + v[4*g+1][j] + v[4*g+2][j] + v[4*g+3][j];
#pragma unroll
            for (int r = 0; r < 4; r++)
#pragma unroll
                for (int j = 0; j < 8; j++)
                    v[4*g+r][j] = fmaxf((s[j] + v[4*g+r][j]) * 0.2f + bv[j], 0.f);
        }
    } else {
#pragma unroll
        for (int r = 0; r < 8; r++)
#pragma unroll
            for (int j = 0; j < 8; j++)
                v[r][j] = fmaxf(v[r][j] + bv[j], 0.f);
    }
}

__device__ __forceinline__ void store_at_T(float* at, float v[8][8], int tx, int ty)
{
#pragma unroll
    for (int j = 0; j < 8; j++) {
        float* q = at + (tx + j) * 132 + ty;
        *(float4*)(q)     = make_float4(v[0][j], v[1][j], v[2][j], v[3][j]);
        *(float4*)(q + 4) = make_float4(v[4][j], v[5][j], v[6][j], v[7][j]);
    }
}

// ---------------------------------------------------------------------------
// FF path (unchanged, measured good)
// ---------------------------------------------------------------------------
template <int K1, int MIX34>
__global__ __launch_bounds__(256) void fused_ff(
    const float* __restrict__ in,
    const float* __restrict__ W1, const float* __restrict__ b1,
    const float* __restrict__ W2, const float* __restrict__ b2,
    const float* __restrict__ W3, const float* __restrict__ b3,
    const float* __restrict__ W4, const float* __restrict__ b4,
    __half* __restrict__ out)
{
    extern __shared__ float s[];
    float* wa = s;
    float* wb = wa + 128 * 128;
    float* at = wb + 128 * 128;
    const int tid = threadIdx.x;
    const long bm = (long)blockIdx.x * 128;
    const int tx = (tid & 15) * 8;
    const int ty = (tid >> 4) * 8;

    for (int i = tid; i < K1 * 32; i += 256)
        ((float4*)wa)[i] = ((const float4*)W1)[i];
    for (int i = tid; i < 4096; i += 256)
        ((float4*)wb)[i] = ((const float4*)W2)[i];
    {
        const int r = tid >> 1;
        const int h = tid & 1;
        const int C = K1 / 2;
        const float* p = in + (bm + r) * K1 + h * C;
#pragma unroll
        for (int c = 0; c < C; c += 4) {
            float4 vv = *(const float4*)(p + c);
            at[(h * C + c + 0) * 132 + r] = vv.x;
            at[(h * C + c + 1) * 132 + r] = vv.y;
            at[(h * C + c + 2) * 132 + r] = vv.z;
            at[(h * C + c + 3) * 132 + r] = vv.w;
        }
    }
    __syncthreads();

    u64 acc[4][8];
    float v[8][8];

    smem_gemm(at, wa, K1, tx, ty, acc);
    __syncthreads();
    unpack_epi(acc, b1, tx, 0, v);
    store_at_T(at, v, tx, ty);
    for (int i = tid; i < 4096; i += 256)
        ((float4*)wa)[i] = ((const float4*)W3)[i];
    __syncthreads();

    smem_gemm(at, wb, 128, tx, ty, acc);
    __syncthreads();
    unpack_epi(acc, b2, tx, 0, v);
    store_at_T(at, v, tx, ty);
    for (int i = tid; i < 4096; i += 256)
        ((float4*)wb)[i] = ((const float4*)W4)[i];
    __syncthreads();

    smem_gemm(at, wa, 128, tx, ty, acc);
    __syncthreads();
    unpack_epi(acc, b3, tx, MIX34, v);
    store_at_T(at, v, tx, ty);
    __syncthreads();

    smem_gemm(at, wb, 128, tx, ty, acc);
    unpack_epi(acc, b4, tx, MIX34, v);
#pragma unroll
    for (int r = 0; r < 8; r++) {
        __half2 h4[4];
#pragma unroll
        for (int j2 = 0; j2 < 4; j2++)
            h4[j2] = __floats2half2_rn(v[r][2*j2], v[r][2*j2+1]);
        __half* q = out + (bm + ty + r) * 128 + tx;
        *(uint4*)q = *(uint4*)h4;
    }
}

// ---------------------------------------------------------------------------
// Shared LSTM half-matmul: 5 seqs, 128 K-values (this half's matrix), output
// the per-seq (colA,colB) scalar sums. Weights: 16 k2 in regs + 48 k2 fp16
// SMEM at wbase [q*512 + col-pair layout]. obase[i*128 + k].
// ---------------------------------------------------------------------------
__device__ __forceinline__ void half_mm(
    const float* obase, const u64* wreg, const unsigned* wbase, int c2,
    float2 zout[SPB])
{
    u64 aA0 = 0, aA1 = 0, aA2 = 0, aA3 = 0, aA4 = 0;
    u64 aB0 = 0, aB1 = 0, aB2 = 0, aB3 = 0, aB4 = 0;

#pragma unroll
    for (int k2 = 0; k2 < 16; k2 += 2) {
        ulonglong2 h0 = *(const ulonglong2*)&obase[0 * 128 + 2 * k2];
        ulonglong2 h1 = *(const ulonglong2*)&obase[1 * 128 + 2 * k2];
        ulonglong2 h2 = *(const ulonglong2*)&obase[2 * 128 + 2 * k2];
        ulonglong2 h3 = *(const ulonglong2*)&obase[3 * 128 + 2 * k2];
        ulonglong2 h4 = *(const ulonglong2*)&obase[4 * 128 + 2 * k2];
        u64 wA0 = wreg[2 * k2],     wB0 = wreg[2 * k2 + 1];
        u64 wA1 = wreg[2 * k2 + 2], wB1 = wreg[2 * k2 + 3];
        fma2(aA0, h0.x, wA0); fma2(aA0, h0.y, wA1);
        fma2(aB0, h0.x, wB0); fma2(aB0, h0.y, wB1);
        fma2(aA1, h1.x, wA0); fma2(aA1, h1.y, wA1);
        fma2(aB1, h1.x, wB0); fma2(aB1, h1.y, wB1);
        fma2(aA2, h2.x, wA0); fma2(aA2, h2.y, wA1);
        fma2(aB2, h2.x, wB0); fma2(aB2, h2.y, wB1);
        fma2(aA3, h3.x, wA0); fma2(aA3, h3.y, wA1);
        fma2(aB3, h3.x, wB0); fma2(aB3, h3.y, wB1);
        fma2(aA4, h4.x, wA0); fma2(aA4, h4.y, wA1);
        fma2(aB4, h4.x, wB0); fma2(aB4, h4.y, wB1);
    }
#pragma unroll 4
    for (int q = 0; q < 48; q += 2) {
        uint2 wa_ = *(const uint2*)&wbase[q * 512 + c2];
        uint2 wb_ = *(const uint2*)&wbase[(q + 1) * 512 + c2];
        u64 wA0 = h2f2(wa_.x), wB0 = h2f2(wa_.y);
        u64 wA1 = h2f2(wb_.x), wB1 = h2f2(wb_.y);
        int ko = 32 + 2 * q;
        ulonglong2 h0 = *(const ulonglong2*)&obase[0 * 128 + ko];
        ulonglong2 h1 = *(const ulonglong2*)&obase[1 * 128 + ko];
        ulonglong2 h2 = *(const ulonglong2*)&obase[2 * 128 + ko];
        ulonglong2 h3 = *(const ulonglong2*)&obase[3 * 128 + ko];
        ulonglong2 h4 = *(const ulonglong2*)&obase[4 * 128 + ko];
        fma2(aA0, h0.x, wA0); fma2(aA0, h0.y, wA1);
        fma2(aB0, h0.x, wB0); fma2(aB0, h0.y, wB1);
        fma2(aA1, h1.x, wA0); fma2(aA1, h1.y, wA1);
        fma2(aB1, h1.x, wB0); fma2(aB1, h1.y, wB1);
        fma2(aA2, h2.x, wA0); fma2(aA2, h2.y, wA1);
        fma2(aB2, h2.x, wB0); fma2(aB2, h2.y, wB1);
        fma2(aA3, h3.x, wA0); fma2(aA3, h3.y, wA1);
        fma2(aB3, h3.x, wB0); fma2(aB3, h3.y, wB1);
        fma2(aA4, h4.x, wA0); fma2(aA4, h4.y, wA1);
        fma2(aB4, h4.x, wB0); fma2(aB4, h4.y, wB1);
    }
    float l, h;
    up2(l, h, aA0); zout[0].x = l + h; up2(l, h, aB0); zout[0].y = l + h;
    up2(l, h, aA1); zout[1].x = l + h; up2(l, h, aB1); zout[1].y = l + h;
    up2(l, h, aA2); zout[2].x = l + h; up2(l, h, aB2); zout[2].y = l + h;
    up2(l, h, aA3); zout[3].x = l + h; up2(l, h, aB3); zout[3].y = l + h;
    up2(l, h, aA4); zout[4].x = l + h; up2(l, h, aB4); zout[4].y = l + h;
}

// ---------------------------------------------------------------------------
// LSTM v8: warp-specialized pipeline.
//   kh0 (tid<256):  zh(t) = Whh·h(t-1) -> bar.sync(1,256) -> gates(t)
//   kh1 (tid>=256): zx(t+1) = Wih·x(t+1) (one step AHEAD, off critical path),
//                   restage xsm[t&1] <- x(t+2)
//   ONE full barrier per step orders: zx(t+1)/xsm writes & h(t) before step t+1.
// Buffers: xsm fp32 x2, zx fp16 x2, zh fp32 x1.  SMEM 227328 B.
// ---------------------------------------------------------------------------
#define LSTM8_SMEM_BYTES (196608 + 2560 + 2560 + 5120 + 10240 + 10240)

__global__ __launch_bounds__(512, 1) void lstm8(
    const __half* __restrict__ x_n, const float* __restrict__ Wih_n,
    const float* __restrict__ Whh_n, const float* __restrict__ b_n, __half* __restrict__ hn,
    const __half* __restrict__ x_e, const float* __restrict__ Wih_e,
    const float* __restrict__ Whh_e, const float* __restrict__ b_e, __half* __restrict__ he)
{
    extern __shared__ float sm[];
    unsigned* wsm = (unsigned*)sm;            // 49152 u32: [kh*24576 + q*512 + col]
    float* hsm  = (float*)(wsm + 49152);      // 640:  [i*128 + k] = h(t-1)
    float* csm  = hsm + 640;                  // 640
    float* xsm  = csm + 640;                  // 1280: 2 buffers [b*640 + i*128 + k]
    float* zh   = xsm + 1280;                 // 2560: [i*512 + c]
    __half* zxh = (__half*)(zh + 2560);       // 5120 halves: [b*2560 + i*512 + c]

    const int tid = threadIdx.x;
    const int col = tid & 255;
    const int kh  = tid >> 8;
    const int c2  = 2 * col;

    const float* Wih; const float* Whh; const float* bias;
    const __half* x; __half* out;
    int seq0, nseq, is_node;

    if (blockIdx.x < 26) {
        Wih = Wih_n; Whh = Whh_n; bias = b_n; x = x_n; out = hn;
        seq0 = blockIdx.x * SPB; nseq = 128; is_node = 1;
    } else {
        Wih = Wih_e; Whh = Whh_e; bias = b_e; x = x_e; out = he;
        seq0 = (blockIdx.x - 26) * SPB; nseq = 512; is_node = 0;
    }
    const long xstep = is_node ? (4 * 128) : (16 * 128);   // halves per t

    // ---- stage SMEM weights (rows 32..127 of each half's matrix, fp16) ----
    for (int idx = tid; idx < 49152; idx += 512) {
        int khi = idx / 24576;
        int rem = idx - khi * 24576;
        int k2s = rem >> 9, c = rem & 511;
        const float* Wsrc = khi ? Wih : Whh;
        __half2 hh = __floats2half2_rn(Wsrc[(size_t)(32 + 2 * k2s) * 512 + c],
                                       Wsrc[(size_t)(33 + 2 * k2s) * 512 + c]);
        wsm[idx] = *(unsigned*)&hh;
    }
    // ---- register weights: rows 0..31 of this thread's half (fp32) ----
    u64 wreg[32];
    {
        const float* Wmy = kh ? Wih : Whh;
#pragma unroll
        for (int k2 = 0; k2 < 16; k2++) {
            float2 la = *(const float2*)&Wmy[(size_t)(2 * k2) * 512 + c2];
            float2 lb = *(const float2*)&Wmy[(size_t)(2 * k2 + 1) * 512 + c2];
            wreg[2 * k2]     = pk2(la.x, lb.x);
            wreg[2 * k2 + 1] = pk2(la.y, lb.y);
        }
    }
    const unsigned* wbase = wsm + kh * 24576;

    // row bases for the 5 sequences (for out writes + x addressing)
    long rowb[SPB];
    int vald[SPB];
#pragma unroll
    for (int i = 0; i < SPB; i++) {
        int sq = seq0 + i;
        vald[i] = (sq < nseq);
        rowb[i] = is_node ? ((long)(sq >> 2) * 2048 + (sq & 3))
                          : ((long)(sq >> 4) * 8192 + (sq & 15));
    }

    for (int idx = tid; idx < 640; idx += 512) { hsm[idx] = 0.f; csm[idx] = 0.f; }

    // prologue: stage xsm[0]=x(0), xsm[1]=x(1)
    for (int idx = tid; idx < 1280; idx += 512) {
        int b = idx >= 640;
        int j = b ? (idx - 640) : idx;
        int i = j >> 7, k = j & 127;
        __half v = vald[i] ? x[rowb[i] * 128 + (long)b * xstep + k] : __half(0);
        xsm[b * 640 + j] = __half2float(v);
    }
    __syncthreads();

    // prologue: kh1 computes zx(0) -> zxh[0]
    if (kh == 1) {
        float2 z[SPB];
        half_mm(xsm, wreg, wbase, c2, z);
#pragma unroll
        for (int i = 0; i < SPB; i++) {
            __half2 hh = __floats2half2_rn(z[i].x, z[i].y);
            ((unsigned*)zxh)[i * 256 + col] = *(unsigned*)&hh;
        }
    }
    // kh1 x-restage assignment (covers (i_a, kk) + seq-4 duty for lt<64)
    const int lt  = tid & 255;
    const int i_a = lt >> 6;
    const int kk  = lt & 63;
    const int va  = vald[i_a];
    const int vb  = (lt < 64) && vald[4];
    const __half* pa = x + rowb[i_a] * 128 + 2 * kk;
    const __half* pb = x + rowb[4] * 128 + 2 * kk;
    __syncthreads();

    for (int t = 0; t < 512; t++) {
        if (kh == 0) {
            // ---- critical path: Whh·h(t-1) -> zh ----
            float2 z[SPB];
            half_mm(hsm, wreg, wbase, c2, z);
#pragma unroll
            for (int i = 0; i < SPB; i++)
                *(float2*)&zh[i * 512 + c2] = z[i];
            asm volatile("bar.sync 1, 256;" ::: "memory");
            // ---- gates(t): z = zh + zx[t&1] + bias ----
            const __half* zxb = zxh + (t & 1) * 2560;
#pragma unroll 1
            for (int q = tid; q < SPB * 128; q += 256) {
                int i = q >> 7, hh_ = q & 127;
                const float* z0 = zh + i * 512;
                const __half* z1 = zxb + i * 512;
                float zi = clamp15(z0[hh_]       + __half2float(z1[hh_])       + bias[hh_]);
                float zf = clamp15(z0[128 + hh_] + __half2float(z1[128 + hh_]) + bias[128 + hh_]);
                float zg = clamp15(z0[256 + hh_] + __half2float(z1[256 + hh_]) + bias[256 + hh_]);
                float zo = clamp15(z0[384 + hh_] + __half2float(z1[384 + hh_]) + bias[384 + hh_]);
                float ei = pexp(-zi);
                float ef = pexp(-zf);
                float g2 = pexp(2.0f * zg);
                float eo = pexp(-zo);
                float pi_ = 1.f + ei, pf_ = 1.f + ef, pg_ = g2 + 1.f;
                float cold = csm[q];
                float num = cold * pi_ * pg_ + (g2 - 1.f) * pf_;
                float cn  = num * rcpa(pf_ * pi_ * pg_);
                float cc  = clamp15(cn);
                float T   = pexp(2.0f * cc);
                float hv  = (T - 1.f) * rcpa((T + 1.f) * (1.f + eo));
                csm[q] = cn;
                hsm[q] = hv;
                if (vald[i])
                    out[rowb[i] * 128 + (long)t * xstep + hh_] = __float2half(hv);
            }
        } else {
            // ---- off critical path: Wih·x(t+1) -> zxh[(t+1)&1] ----
            int tp = (t + 2 < 512) ? (t + 2) : 511;   // prefetch x(t+2)
            unsigned xra = va ? *(const unsigned*)(pa + (long)tp * xstep) : 0u;
            unsigned xrb = vb ? *(const unsigned*)(pb + (long)tp * xstep) : 0u;

            float2 z[SPB];
            half_mm(xsm + ((t + 1) & 1) * 640, wreg, wbase, c2, z);
            unsigned* zxw = (unsigned*)zxh + ((t + 1) & 1) * 1280;
#pragma unroll
            for (int i = 0; i < SPB; i++) {
                __half2 hh = __floats2half2_rn(z[i].x, z[i].y);
                zxw[i * 256 + col] = *(unsigned*)&hh;
            }
            // restage xsm[t&1] <- x(t+2)
            {
                float* xb = xsm + (t & 1) * 640;
                float2 f = __half22float2(*(const __half2*)&xra);
                *(float2*)&xb[i_a * 128 + 2 * kk] = f;
                if (lt < 64) {
                    float2 g = __half22float2(*(const __half2*)&xrb);
                    *(float2*)&xb[4 * 128 + 2 * kk] = g;
                }
            }
        }
        __syncthreads();
    }
}

// ---------------------------------------------------------------------------
// Classifier (r7/r13 version — measured best): gather + Wc1 + relu + Wc2.
// ---------------------------------------------------------------------------
__global__ __launch_bounds__(256) void c1final(
    const __half* __restrict__ hn, const __half* __restrict__ he,
    const float* __restrict__ Wc1, const float* __restrict__ bc1,
    const float* __restrict__ Wc2, const float* __restrict__ bc2,
    float* __restrict__ out)
{
    extern __shared__ float s[];
    float* hn_s = s;               // 16*128
    float* As   = hn_s + 2048;     // 16*68
    float* Bs   = As + 16 * 68;    // 16*256
    float* ct   = Bs + 16 * 256;   // 256*68
    float* wc2  = ct + 256 * 68;   // 256*8
    const int tid = threadIdx.x;
    const long bm = (long)blockIdx.x * 64;
    const int tx = (tid & 31) * 8;
    const int ty = (tid >> 5) * 8;

    for (int i = tid; i < 512; i += 256)
        ((float4*)wc2)[i] = ((const float4*)Wc2)[i];

    {
        const long bt0 = bm >> 4;
        const __half* hp = hn + bt0 * 4 * 128 + tid * 8;
        uint4 raw = *(const uint4*)hp;
        const __half2* h2p = (const __half2*)&raw;
        float* q = hn_s + tid * 8;
#pragma unroll
        for (int j = 0; j < 4; j++) {
            float2 f = __half22float2(h2p[j]);
            q[2*j] = f.x; q[2*j+1] = f.y;
        }
    }

    const int arow = tid >> 2;
    const int acol = (tid & 3) * 4;
    const long row = bm + arow;
    const int  e   = arow & 15;
    const int  g   = arow >> 4;
    const float* seg0 = hn_s + (g * 4 + (e >> 2)) * 128;
    const float* seg1 = hn_s + (g * 4 + (e & 3)) * 128;
    const __half* seg2 = he + row * 128;

    const int brow = tid >> 4;
    const int bcol = (tid & 15) * 16;

    u64 acc[4][8];
#pragma unroll
    for (int i = 0; i < 4; i++)
#pragma unroll
        for (int j = 0; j < 8; j++) acc[i][j] = 0ull;

    __syncthreads();

    for (int k0 = 0; k0 < 384; k0 += 16) {
        float4 av;
        if (k0 < 128) {
            av = *(const float4*)(seg0 + k0 + acol);
        } else if (k0 < 256) {
            av = *(const float4*)(seg1 + (k0 - 128) + acol);
        } else {
            const __half* p = seg2 + (k0 - 256) + acol;
            uint2 raw = *(const uint2*)p;
            float2 f01 = __half22float2(*(const __half2*)&raw.x);
            float2 f23 = __half22float2(*(const __half2*)&raw.y);
            av = make_float4(f01.x, f01.y, f23.x, f23.y);
        }
        const float* bp = Wc1 + (size_t)(k0 + brow) * 256 + bcol;
        float4 bv0 = *(const float4*)(bp);
        float4 bv1 = *(const float4*)(bp + 4);
        float4 bv2 = *(const float4*)(bp + 8);
        float4 bv3 = *(const float4*)(bp + 12);
        As[(acol + 0) * 68 + arow] = av.x;
        As[(acol + 1) * 68 + arow] = av.y;
        As[(acol + 2) * 68 + arow] = av.z;
        As[(acol + 3) * 68 + arow] = av.w;
        float* bq = Bs + brow * 256 + bcol;
        *(float4*)(bq)      = bv0;
        *(float4*)(bq + 4)  = bv1;
        *(float4*)(bq + 8)  = bv2;
        *(float4*)(bq + 12) = bv3;
        __syncthreads();

#pragma unroll
        for (int kk = 0; kk < 16; kk++) {
            ulonglong2 aa = *(const ulonglong2*)&As[kk * 68 + ty];
            ulonglong2 ab = *(const ulonglong2*)&As[kk * 68 + ty + 4];
            float4 c0 = *(const float4*)&Bs[kk * 256 + tx];
            float4 c1 = *(const float4*)&Bs[kk * 256 + tx + 4];
            u64 bd[8];
            bd[0] = pk2(c0.x, c0.x); bd[1] = pk2(c0.y, c0.y);
            bd[2] = pk2(c0.z, c0.z); bd[3] = pk2(c0.w, c0.w);
            bd[4] = pk2(c1.x, c1.x); bd[5] = pk2(c1.y, c1.y);
            bd[6] = pk2(c1.z, c1.z); bd[7] = pk2(c1.w, c1.w);
            u64 ap[4] = { aa.x, aa.y, ab.x, ab.y };
#pragma unroll
            for (int i = 0; i < 4; i++)
#pragma unroll
                for (int j = 0; j < 8; j++)
                    fma2(acc[i][j], ap[i], bd[j]);
        }
        __syncthreads();
    }

    float v[8][8];
#pragma unroll
    for (int i = 0; i < 4; i++)
#pragma unroll
        for (int j = 0; j < 8; j++)
            up2(v[2 * i][j], v[2 * i + 1][j], acc[i][j]);
    float bv[8];
    *(float4*)&bv[0] = *(const float4*)&bc1[tx];
    *(float4*)&bv[4] = *(const float4*)&bc1[tx + 4];
#pragma unroll
    for (int j = 0; j < 8; j++) {
        float* q = ct + (tx + j) * 68 + ty;
        *(float4*)(q)     = make_float4(fmaxf(v[0][j]+bv[j],0.f), fmaxf(v[1][j]+bv[j],0.f),
                                        fmaxf(v[2][j]+bv[j],0.f), fmaxf(v[3][j]+bv[j],0.f));
        *(float4*)(q + 4) = make_float4(fmaxf(v[4][j]+bv[j],0.f), fmaxf(v[5][j]+bv[j],0.f),
                                        fmaxf(v[6][j]+bv[j],0.f), fmaxf(v[7][j]+bv[j],0.f));
    }
    __syncthreads();

    {
        const int r = tid >> 2;
        const int c = (tid & 3) * 2;
        float f0 = bc2[c], f1 = bc2[c + 1];
#pragma unroll 8
        for (int k = 0; k < 256; k++) {
            float a = ct[k * 68 + r];
            f0 += a * wc2[k * 8 + c];
            f1 += a * wc2[k * 8 + c + 1];
        }
        float* q = out + (bm + r) * 8 + c;
        q[0] = f0; q[1] = f1;
    }
}

// Tiny dummy kernel: keeps the profiled slot (idx3) on lstm8.
__global__ void dummy_k(float* p) { p[threadIdx.x] = 0.f; }

// ---------------------------------------------------------------------------
// Launch: dummy, FF-edge, FF-node, LSTM8 (idx3 = profiled), classifier.
// ---------------------------------------------------------------------------
extern "C" void kernel_launch(void* const* d_in, const int* in_sizes, int n_in,
                              void* d_out, int out_size)
{
    const float* x_seq = (const float*)d_in[0];
    const float* ea    = (const float*)d_in[1];
    const float* Wn1   = (const float*)d_in[2];
    const float* bn1   = (const float*)d_in[3];
    const float* Wn2   = (const float*)d_in[4];
    const float* bn2   = (const float*)d_in[5];
    const float* We1   = (const float*)d_in[6];
    const float* be1   = (const float*)d_in[7];
    const float* We2   = (const float*)d_in[8];
    const float* be2   = (const float*)d_in[9];
    const float* Wg1   = (const float*)d_in[10];
    const float* bg1   = (const float*)d_in[11];
    const float* Wg2   = (const float*)d_in[12];
    const float* bg2   = (const float*)d_in[13];
    const float* Wef1  = (const float*)d_in[14];
    const float* bef1  = (const float*)d_in[15];
    const float* Wef2  = (const float*)d_in[16];
    const float* bef2  = (const float*)d_in[17];
    const float* Wih_n = (const float*)d_in[18];
    const float* Whh_n = (const float*)d_in[19];
    const float* b_n   = (const float*)d_in[20];
    const float* Wih_e = (const float*)d_in[21];
    const float* Whh_e = (const float*)d_in[22];
    const float* b_e   = (const float*)d_in[23];
    const float* Wc1   = (const float*)d_in[24];
    const float* bc1   = (const float*)d_in[25];
    const float* Wc2   = (const float*)d_in[26];
    const float* bc2   = (const float*)d_in[27];
    float* out = (float*)d_out;

    (void)in_sizes; (void)n_in; (void)out_size;

    const int SMF   = (128 * 128 * 2 + 128 * 132) * 4;
    const int SMC1F = (2048 + 16*68 + 16*256 + 256*68 + 256*8) * 4;
    cudaFuncSetAttribute(fused_ff<8, 0>,  cudaFuncAttributeMaxDynamicSharedMemorySize, SMF);
    cudaFuncSetAttribute(fused_ff<16, 1>, cudaFuncAttributeMaxDynamicSharedMemorySize, SMF);
    cudaFuncSetAttribute(lstm8,   cudaFuncAttributeMaxDynamicSharedMemorySize, LSTM8_SMEM_BYTES);
    cudaFuncSetAttribute(c1final, cudaFuncAttributeMaxDynamicSharedMemorySize, SMC1F);

    __half* e4 = (__half*)(g_arena + OFF_E4);
    __half* x4 = (__half*)(g_arena + OFF_X4);
    __half* hn = (__half*)(g_arena + OFF_HN);
    __half* he = (__half*)(g_arena + OFF_HE);

    // idx0: dummy slot shim
    dummy_k<<<1, 32>>>(g_arena + OFF_SLACK);
    // idx1: edge FF path ea -> e4 (fp16)
    fused_ff<8, 0><<<2048, 256, SMF>>>(ea,
        We1, be1, We2, be2, Wef1, bef1, Wef2, bef2, e4);
    // idx2: node FF path x_seq -> x4 (fp16, graph-conv mixes fused)
    fused_ff<16, 1><<<512, 256, SMF>>>(x_seq,
        Wn1, bn1, Wn2, bn2, Wg1, bg1, Wg2, bg2, x4);
    // idx3: warp-specialized pipelined LSTM [profiled]
    lstm8<<<129, 512, LSTM8_SMEM_BYTES>>>(x4, Wih_n, Whh_n, b_n, hn,
                                          e4, Wih_e, Whh_e, b_e, he);
    // idx4: classifier (r7 version)
    c1final<<<4096, 256, SMC1F>>>(hn, he, Wc1, bc1, Wc2, bc2, out);
}

// round 16
// speedup vs baseline: 1.0681x; 1.0438x over previous
#include <cuda_runtime.h>
#include <cuda_fp16.h>
#include <math.h>

// ---------------------------------------------------------------------------
// Problem: B=32,T=512,N=4,E=16, NI=16,EI=8, HN=HE=128, MH=256, C=8
// HW model: statics HOST-resident (C2C ~230GB/s). Corrected floors (18.9
// GMAC/cyc chip fp32x2): LSTM 1.45ms (meas 2.77, 3 architectures tied ->
// jointly fma/LDS/issue bound, left alone), c1final 0.76 (meas 1.43,
// latency-exposed gmem tile loads -> THIS round: reg prefetch), FF 0.45.
// ---------------------------------------------------------------------------

typedef unsigned long long u64;

#define SPB 5

// ---- scratch arena (host-resident), fp16 payloads ----
#define OFF_E4    0L
#define OFF_X4    16777216L
#define OFF_HN    20971520L
#define OFF_HE    25165824L
#define OFF_SLACK 41943040L
__device__ float g_arena[41943104];

// ---- packed fp32x2 helpers ----
__device__ __forceinline__ u64 pk2(float lo, float hi) {
    u64 r; asm("mov.b64 %0, {%1,%2};" : "=l"(r) : "f"(lo), "f"(hi)); return r;
}
__device__ __forceinline__ void up2(float& lo, float& hi, u64 v) {
    asm("mov.b64 {%0,%1}, %2;" : "=f"(lo), "=f"(hi) : "l"(v));
}
__device__ __forceinline__ void fma2(u64& c, u64 a, u64 b) {
    asm("fma.rn.f32x2 %0, %1, %2, %0;" : "+l"(c) : "l"(a), "l"(b));
}
__device__ __forceinline__ u64 h2f2(unsigned h) {
    float2 f = __half22float2(*(const __half2*)&h);
    return pk2(f.x, f.y);
}

// ---- MUFU-free exp (FMA pipe), err ~1e-7 for |x|<=~40 ----
__device__ __forceinline__ float pexp(float x) {
    float t = x * 1.44269504088896f;
    float k = t + 12582912.0f;
    int   e = __float_as_int(k) - 0x4B400000;
    float n = k - 12582912.0f;
    float f = t - n;
    float p =              1.54035304e-4f;
    p = fmaf(p, f, 1.33335581e-3f);
    p = fmaf(p, f, 9.61812911e-3f);
    p = fmaf(p, f, 5.55041087e-2f);
    p = fmaf(p, f, 2.40226507e-1f);
    p = fmaf(p, f, 6.93147181e-1f);
    p = fmaf(p, f, 1.0f);
    float s = __int_as_float((e + 127) << 23);
    return p * s;
}
__device__ __forceinline__ float rcpa(float x) {
    float r; asm("rcp.approx.f32 %0, %1;" : "=f"(r) : "f"(x)); return r;
}
__device__ __forceinline__ float clamp15(float x) {
    return fminf(fmaxf(x, -15.f), 15.f);
}

// ---------------------------------------------------------------------------
// SMEM microtile GEMM (FF path): at[k*132+r], w[k*128+c]
// ---------------------------------------------------------------------------
__device__ __forceinline__ void smem_gemm(
    const float* at, const float* w, int K, int tx, int ty, u64 acc[4][8])
{
#pragma unroll
    for (int i = 0; i < 4; i++)
#pragma unroll
        for (int j = 0; j < 8; j++) acc[i][j] = 0ull;
#pragma unroll 8
    for (int k = 0; k < K; k++) {
        ulonglong2 aa = *(const ulonglong2*)&at[k * 132 + ty];
        ulonglong2 ab = *(const ulonglong2*)&at[k * 132 + ty + 4];
        float4 c0 = *(const float4*)&w[k * 128 + tx];
        float4 c1 = *(const float4*)&w[k * 128 + tx + 4];
        u64 bd[8];
        bd[0] = pk2(c0.x, c0.x); bd[1] = pk2(c0.y, c0.y);
        bd[2] = pk2(c0.z, c0.z); bd[3] = pk2(c0.w, c0.w);
        bd[4] = pk2(c1.x, c1.x); bd[5] = pk2(c1.y, c1.y);
        bd[6] = pk2(c1.z, c1.z); bd[7] = pk2(c1.w, c1.w);
        u64 ap[4] = { aa.x, aa.y, ab.x, ab.y };
#pragma unroll
        for (int i = 0; i < 4; i++)
#pragma unroll
            for (int j = 0; j < 8; j++)
                fma2(acc[i][j], ap[i], bd[j]);
    }
}

__device__ __forceinline__ void unpack_epi(
    u64 acc[4][8], const float* bias, int tx, int MIX, float v[8][8])
{
#pragma unroll
    for (int i = 0; i < 4; i++)
#pragma unroll
        for (int j = 0; j < 8; j++)
            up2(v[2 * i][j], v[2 * i + 1][j], acc[i][j]);
    float bv[8];
    *(float4*)&bv[0] = *(const float4*)&bias[tx];
    *(float4*)&bv[4] = *(const float4*)&bias[tx + 4];
    if (MIX) {
#pragma unroll
        for (int g = 0; g < 2; g++) {
            float s[8];
#pragma unroll
            for (int j = 0; j < 8; j++)
                s[j] = v[4*g][j] + v[4*g+1][j] + v[4*g+2][j] + v[4*g+3][j];
#pragma unroll
            for (int r = 0; r < 4; r++)
#pragma unroll
                for (int j = 0; j < 8; j++)
                    v[4*g+r][j] = fmaxf((s[j] + v[4*g+r][j]) * 0.2f + bv[j], 0.f);
        }
    } else {
#pragma unroll
        for (int r = 0; r < 8; r++)
#pragma unroll
            for (int j = 0; j < 8; j++)
                v[r][j] = fmaxf(v[r][j] + bv[j], 0.f);
    }
}

__device__ __forceinline__ void store_at_T(float* at, float v[8][8], int tx, int ty)
{
#pragma unroll
    for (int j = 0; j < 8; j++) {
        float* q = at + (tx + j) * 132 + ty;
        *(float4*)(q)     = make_float4(v[0][j], v[1][j], v[2][j], v[3][j]);
        *(float4*)(q + 4) = make_float4(v[4][j], v[5][j], v[6][j], v[7][j]);
    }
}

// ---------------------------------------------------------------------------
// FF path (unchanged, measured good)
// ---------------------------------------------------------------------------
template <int K1, int MIX34>
__global__ __launch_bounds__(256) void fused_ff(
    const float* __restrict__ in,
    const float* __restrict__ W1, const float* __restrict__ b1,
    const float* __restrict__ W2, const float* __restrict__ b2,
    const float* __restrict__ W3, const float* __restrict__ b3,
    const float* __restrict__ W4, const float* __restrict__ b4,
    __half* __restrict__ out)
{
    extern __shared__ float s[];
    float* wa = s;
    float* wb = wa + 128 * 128;
    float* at = wb + 128 * 128;
    const int tid = threadIdx.x;
    const long bm = (long)blockIdx.x * 128;
    const int tx = (tid & 15) * 8;
    const int ty = (tid >> 4) * 8;

    for (int i = tid; i < K1 * 32; i += 256)
        ((float4*)wa)[i] = ((const float4*)W1)[i];
    for (int i = tid; i < 4096; i += 256)
        ((float4*)wb)[i] = ((const float4*)W2)[i];
    {
        const int r = tid >> 1;
        const int h = tid & 1;
        const int C = K1 / 2;
        const float* p = in + (bm + r) * K1 + h * C;
#pragma unroll
        for (int c = 0; c < C; c += 4) {
            float4 vv = *(const float4*)(p + c);
            at[(h * C + c + 0) * 132 + r] = vv.x;
            at[(h * C + c + 1) * 132 + r] = vv.y;
            at[(h * C + c + 2) * 132 + r] = vv.z;
            at[(h * C + c + 3) * 132 + r] = vv.w;
        }
    }
    __syncthreads();

    u64 acc[4][8];
    float v[8][8];

    smem_gemm(at, wa, K1, tx, ty, acc);
    __syncthreads();
    unpack_epi(acc, b1, tx, 0, v);
    store_at_T(at, v, tx, ty);
    for (int i = tid; i < 4096; i += 256)
        ((float4*)wa)[i] = ((const float4*)W3)[i];
    __syncthreads();

    smem_gemm(at, wb, 128, tx, ty, acc);
    __syncthreads();
    unpack_epi(acc, b2, tx, 0, v);
    store_at_T(at, v, tx, ty);
    for (int i = tid; i < 4096; i += 256)
        ((float4*)wb)[i] = ((const float4*)W4)[i];
    __syncthreads();

    smem_gemm(at, wa, 128, tx, ty, acc);
    __syncthreads();
    unpack_epi(acc, b3, tx, MIX34, v);
    store_at_T(at, v, tx, ty);
    __syncthreads();

    smem_gemm(at, wb, 128, tx, ty, acc);
    unpack_epi(acc, b4, tx, MIX34, v);
#pragma unroll
    for (int r = 0; r < 8; r++) {
        __half2 h4[4];
#pragma unroll
        for (int j2 = 0; j2 < 4; j2++)
            h4[j2] = __floats2half2_rn(v[r][2*j2], v[r][2*j2+1]);
        __half* q = out + (bm + ty + r) * 128 + tx;
        *(uint4*)q = *(uint4*)h4;
    }
}

// ---------------------------------------------------------------------------
// LSTM v7 (r13, best measured — unchanged): 512 threads, K-SPLIT.
// ---------------------------------------------------------------------------
#define LSTM7_SMEM_BYTES (49152 * 4 + (640 * 3 + 5120) * 4)   // 224768 B

__global__ __launch_bounds__(512, 1) void lstm7(
    const __half* __restrict__ x_n, const float* __restrict__ Wih_n,
    const float* __restrict__ Whh_n, const float* __restrict__ b_n, __half* __restrict__ hn,
    const __half* __restrict__ x_e, const float* __restrict__ Wih_e,
    const float* __restrict__ Whh_e, const float* __restrict__ b_e, __half* __restrict__ he)
{
    extern __shared__ float sm[];
    unsigned* wsm = (unsigned*)sm;            // [kh*24576 + k2s*512 + col], k2s 0..47
    float* hsm = (float*)(wsm + 49152);       // [i*128 + k]
    float* xsm = hsm + 640;                   // [i*128 + k]
    float* csm = xsm + 640;                   // [i*128 + k]
    float* zsm = csm + 640;                   // [kh*2560 + i*512 + c]

    const int tid = threadIdx.x;
    const int col = tid & 255;
    const int kh  = tid >> 8;                 // 0: Whh half, 1: Wih half
    const int c2  = 2 * col;

    const float* Wih; const float* Whh; const float* bias;
    const __half* x; __half* out;
    int seq0, nseq, is_node;

    if (blockIdx.x < 26) {
        Wih = Wih_n; Whh = Whh_n; bias = b_n; x = x_n; out = hn;
        seq0 = blockIdx.x * SPB; nseq = 128; is_node = 1;
    } else {
        Wih = Wih_e; Whh = Whh_e; bias = b_e; x = x_e; out = he;
        seq0 = (blockIdx.x - 26) * SPB; nseq = 512; is_node = 0;
    }
    const long xstep = is_node ? (4 * 128) : (16 * 128);   // halves per t

    for (int idx = tid; idx < 49152; idx += 512) {
        int khi = idx / 24576;
        int rem = idx - khi * 24576;
        int k2s = rem >> 9, c = rem & 511;
        const float* Wsrc = khi ? Wih : Whh;
        __half2 hh = __floats2half2_rn(Wsrc[(size_t)(32 + 2 * k2s) * 512 + c],
                                       Wsrc[(size_t)(33 + 2 * k2s) * 512 + c]);
        wsm[idx] = *(unsigned*)&hh;
    }
    u64 wreg[32];
    {
        const float* Wmy = kh ? Wih : Whh;
#pragma unroll
        for (int k2 = 0; k2 < 16; k2++) {
            float2 la = *(const float2*)&Wmy[(size_t)(2 * k2) * 512 + c2];
            float2 lb = *(const float2*)&Wmy[(size_t)(2 * k2 + 1) * 512 + c2];
            wreg[2 * k2]     = pk2(la.x, lb.x);
            wreg[2 * k2 + 1] = pk2(la.y, lb.y);
        }
    }

    for (int idx = tid; idx < 640; idx += 512) {
        hsm[idx] = 0.f; xsm[idx] = 0.f; csm[idx] = 0.f;
    }

    const int i_a = tid >> 6;                 // 0..7; active if <5
    const int kk  = tid & 63;
    const int act = (i_a < 5);
    int sqa = seq0 + i_a;
    const int va = act && (sqa < nseq);
    long rowa = 0;
    if (act)
        rowa = is_node ? ((long)(sqa >> 2) * 2048 + (sqa & 3))
                       : ((long)(sqa >> 4) * 8192 + (sqa & 15));
    const __half* pa = x + rowa * 128 + 2 * kk;
    {
        unsigned ra = va ? *(const unsigned*)pa : 0u;
        if (act) {
            float2 f = __half22float2(*(const __half2*)&ra);
            *(float2*)&xsm[i_a * 128 + 2 * kk] = f;
        }
    }
    const float* obase = kh ? xsm : hsm;
    float* zpart = zsm + kh * 2560;
    __syncthreads();

    for (int t = 0; t < 512; t++) {
        int tn = (t + 1 < 512) ? (t + 1) : t;
        unsigned xra = va ? *(const unsigned*)(pa + (long)tn * xstep) : 0u;

        u64 aA0 = 0, aA1 = 0, aA2 = 0, aA3 = 0, aA4 = 0;
        u64 aB0 = 0, aB1 = 0, aB2 = 0, aB3 = 0, aB4 = 0;

#pragma unroll
        for (int k2 = 0; k2 < 16; k2 += 2) {
            ulonglong2 h0 = *(const ulonglong2*)&obase[0 * 128 + 2 * k2];
            ulonglong2 h1 = *(const ulonglong2*)&obase[1 * 128 + 2 * k2];
            ulonglong2 h2 = *(const ulonglong2*)&obase[2 * 128 + 2 * k2];
            ulonglong2 h3 = *(const ulonglong2*)&obase[3 * 128 + 2 * k2];
            ulonglong2 h4 = *(const ulonglong2*)&obase[4 * 128 + 2 * k2];
            u64 wA0 = wreg[2 * k2],     wB0 = wreg[2 * k2 + 1];
            u64 wA1 = wreg[2 * k2 + 2], wB1 = wreg[2 * k2 + 3];
            fma2(aA0, h0.x, wA0); fma2(aA0, h0.y, wA1);
            fma2(aB0, h0.x, wB0); fma2(aB0, h0.y, wB1);
            fma2(aA1, h1.x, wA0); fma2(aA1, h1.y, wA1);
            fma2(aB1, h1.x, wB0); fma2(aB1, h1.y, wB1);
            fma2(aA2, h2.x, wA0); fma2(aA2, h2.y, wA1);
            fma2(aB2, h2.x, wB0); fma2(aB2, h2.y, wB1);
            fma2(aA3, h3.x, wA0); fma2(aA3, h3.y, wA1);
            fma2(aB3, h3.x, wB0); fma2(aB3, h3.y, wB1);
            fma2(aA4, h4.x, wA0); fma2(aA4, h4.y, wA1);
            fma2(aB4, h4.x, wB0); fma2(aB4, h4.y, wB1);
        }
        const unsigned* wbase = wsm + kh * 24576;
#pragma unroll 4
        for (int q = 0; q < 48; q += 2) {
            uint2 wa_ = *(const uint2*)&wbase[q * 512 + c2];
            uint2 wb_ = *(const uint2*)&wbase[(q + 1) * 512 + c2];
            u64 wA0 = h2f2(wa_.x), wB0 = h2f2(wa_.y);
            u64 wA1 = h2f2(wb_.x), wB1 = h2f2(wb_.y);
            int ko = 32 + 2 * q;
            ulonglong2 h0 = *(const ulonglong2*)&obase[0 * 128 + ko];
            ulonglong2 h1 = *(const ulonglong2*)&obase[1 * 128 + ko];
            ulonglong2 h2 = *(const ulonglong2*)&obase[2 * 128 + ko];
            ulonglong2 h3 = *(const ulonglong2*)&obase[3 * 128 + ko];
            ulonglong2 h4 = *(const ulonglong2*)&obase[4 * 128 + ko];
            fma2(aA0, h0.x, wA0); fma2(aA0, h0.y, wA1);
            fma2(aB0, h0.x, wB0); fma2(aB0, h0.y, wB1);
            fma2(aA1, h1.x, wA0); fma2(aA1, h1.y, wA1);
            fma2(aB1, h1.x, wB0); fma2(aB1, h1.y, wB1);
            fma2(aA2, h2.x, wA0); fma2(aA2, h2.y, wA1);
            fma2(aB2, h2.x, wB0); fma2(aB2, h2.y, wB1);
            fma2(aA3, h3.x, wA0); fma2(aA3, h3.y, wA1);
            fma2(aB3, h3.x, wB0); fma2(aB3, h3.y, wB1);
            fma2(aA4, h4.x, wA0); fma2(aA4, h4.y, wA1);
            fma2(aB4, h4.x, wB0); fma2(aB4, h4.y, wB1);
        }

        {
            float l, h, zA, zB;
            up2(l, h, aA0); zA = l + h; up2(l, h, aB0); zB = l + h;
            *(float2*)&zpart[0 * 512 + c2] = make_float2(zA, zB);
            up2(l, h, aA1); zA = l + h; up2(l, h, aB1); zB = l + h;
            *(float2*)&zpart[1 * 512 + c2] = make_float2(zA, zB);
            up2(l, h, aA2); zA = l + h; up2(l, h, aB2); zB = l + h;
            *(float2*)&zpart[2 * 512 + c2] = make_float2(zA, zB);
            up2(l, h, aA3); zA = l + h; up2(l, h, aB3); zB = l + h;
            *(float2*)&zpart[3 * 512 + c2] = make_float2(zA, zB);
            up2(l, h, aA4); zA = l + h; up2(l, h, aB4); zB = l + h;
            *(float2*)&zpart[4 * 512 + c2] = make_float2(zA, zB);
        }
        __syncthreads();

        if (act) {
            float2 f = __half22float2(*(const __half2*)&xra);
            *(float2*)&xsm[i_a * 128 + 2 * kk] = f;
        }
#pragma unroll 1
        for (int q = tid; q < SPB * 128; q += 512) {
            int i = q >> 7, hh_ = q & 127;
            const float* z0 = zsm + i * 512;
            const float* z1 = zsm + 2560 + i * 512;
            float zi = clamp15(z0[hh_]       + z1[hh_]       + bias[hh_]);
            float zf = clamp15(z0[128 + hh_] + z1[128 + hh_] + bias[128 + hh_]);
            float zg = clamp15(z0[256 + hh_] + z1[256 + hh_] + bias[256 + hh_]);
            float zo = clamp15(z0[384 + hh_] + z1[384 + hh_] + bias[384 + hh_]);
            float ei = pexp(-zi);
            float ef = pexp(-zf);
            float g2 = pexp(2.0f * zg);
            float eo = pexp(-zo);
            float pi_ = 1.f + ei, pf_ = 1.f + ef, pg_ = g2 + 1.f;
            float cold = csm[q];
            float num = cold * pi_ * pg_ + (g2 - 1.f) * pf_;
            float cn  = num * rcpa(pf_ * pi_ * pg_);
            float cc  = clamp15(cn);
            float T   = pexp(2.0f * cc);
            float hv  = (T - 1.f) * rcpa((T + 1.f) * (1.f + eo));
            csm[q] = cn;
            hsm[q] = hv;
            int sq = seq0 + i;
            if (sq < nseq) {
                long row = is_node ? ((long)(sq >> 2) * 2048 + (sq & 3))
                                   : ((long)(sq >> 4) * 8192 + (sq & 15));
                out[row * 128 + (long)t * xstep + hh_] = __float2half(hv);
            }
        }
        __syncthreads();
    }
}

// ---------------------------------------------------------------------------
// Classifier v4: r7 structure + REGISTER PREFETCH double-buffering of the
// per-tile gmem loads (A-gather + 16-float Wc1 tile) — hides L2/DRAM latency
// under the 16-kk compute phase. __launch_bounds__(256,2) keeps 2 blocks/SM.
// ---------------------------------------------------------------------------
__global__ __launch_bounds__(256, 2) void c1final(
    const __half* __restrict__ hn, const __half* __restrict__ he,
    const float* __restrict__ Wc1, const float* __restrict__ bc1,
    const float* __restrict__ Wc2, const float* __restrict__ bc2,
    float* __restrict__ out)
{
    extern __shared__ float s[];
    float* hn_s = s;               // 16*128
    float* As   = hn_s + 2048;     // 16*68
    float* Bs   = As + 16 * 68;    // 16*256
    float* ct   = Bs + 16 * 256;   // 256*68
    float* wc2  = ct + 256 * 68;   // 256*8
    const int tid = threadIdx.x;
    const long bm = (long)blockIdx.x * 64;
    const int tx = (tid & 31) * 8;
    const int ty = (tid >> 5) * 8;

    for (int i = tid; i < 512; i += 256)
        ((float4*)wc2)[i] = ((const float4*)Wc2)[i];

    {
        const long bt0 = bm >> 4;
        const __half* hp = hn + bt0 * 4 * 128 + tid * 8;
        uint4 raw = *(const uint4*)hp;
        const __half2* h2p = (const __half2*)&raw;
        float* q = hn_s + tid * 8;
#pragma unroll
        for (int j = 0; j < 4; j++) {
            float2 f = __half22float2(h2p[j]);
            q[2*j] = f.x; q[2*j+1] = f.y;
        }
    }

    const int arow = tid >> 2;
    const int acol = (tid & 3) * 4;
    const long row = bm + arow;
    const int  e   = arow & 15;
    const int  g   = arow >> 4;
    const float* seg0 = hn_s + (g * 4 + (e >> 2)) * 128;
    const float* seg1 = hn_s + (g * 4 + (e & 3)) * 128;
    const __half* seg2 = he + row * 128;

    const int brow = tid >> 4;
    const int bcol = (tid & 15) * 16;
    const float* Bp = Wc1 + (size_t)brow * 256 + bcol;

    u64 acc[4][8];
#pragma unroll
    for (int i = 0; i < 4; i++)
#pragma unroll
        for (int j = 0; j < 8; j++) acc[i][j] = 0ull;

    __syncthreads();    // hn_s ready (needed before seg0 preload)

    // preload tile k0=0 into registers
    float4 av_r = *(const float4*)(seg0 + acol);
    float4 bv_r0 = *(const float4*)(Bp);
    float4 bv_r1 = *(const float4*)(Bp + 4);
    float4 bv_r2 = *(const float4*)(Bp + 8);
    float4 bv_r3 = *(const float4*)(Bp + 12);

    for (int k0 = 0; k0 < 384; k0 += 16) {
        // store staged tile
        As[(acol + 0) * 68 + arow] = av_r.x;
        As[(acol + 1) * 68 + arow] = av_r.y;
        As[(acol + 2) * 68 + arow] = av_r.z;
        As[(acol + 3) * 68 + arow] = av_r.w;
        float* bq = Bs + brow * 256 + bcol;
        *(float4*)(bq)      = bv_r0;
        *(float4*)(bq + 4)  = bv_r1;
        *(float4*)(bq + 8)  = bv_r2;
        *(float4*)(bq + 12) = bv_r3;
        __syncthreads();

        // prefetch tile k0+16 (hidden under compute below)
        int k1 = k0 + 16;
        if (k1 < 384) {
            if (k1 < 128) {
                av_r = *(const float4*)(seg0 + k1 + acol);
            } else if (k1 < 256) {
                av_r = *(const float4*)(seg1 + (k1 - 128) + acol);
            } else {
                const __half* p = seg2 + (k1 - 256) + acol;
                uint2 raw = *(const uint2*)p;
                float2 f01 = __half22float2(*(const __half2*)&raw.x);
                float2 f23 = __half22float2(*(const __half2*)&raw.y);
                av_r = make_float4(f01.x, f01.y, f23.x, f23.y);
            }
            const float* bp = Bp + (size_t)k1 * 256;
            bv_r0 = *(const float4*)(bp);
            bv_r1 = *(const float4*)(bp + 4);
            bv_r2 = *(const float4*)(bp + 8);
            bv_r3 = *(const float4*)(bp + 12);
        }

#pragma unroll
        for (int kk = 0; kk < 16; kk++) {
            ulonglong2 aa = *(const ulonglong2*)&As[kk * 68 + ty];
            ulonglong2 ab = *(const ulonglong2*)&As[kk * 68 + ty + 4];
            float4 c0 = *(const float4*)&Bs[kk * 256 + tx];
            float4 c1 = *(const float4*)&Bs[kk * 256 + tx + 4];
            u64 bd[8];
            bd[0] = pk2(c0.x, c0.x); bd[1] = pk2(c0.y, c0.y);
            bd[2] = pk2(c0.z, c0.z); bd[3] = pk2(c0.w, c0.w);
            bd[4] = pk2(c1.x, c1.x); bd[5] = pk2(c1.y, c1.y);
            bd[6] = pk2(c1.z, c1.z); bd[7] = pk2(c1.w, c1.w);
            u64 ap[4] = { aa.x, aa.y, ab.x, ab.y };
#pragma unroll
            for (int i = 0; i < 4; i++)
#pragma unroll
                for (int j = 0; j < 8; j++)
                    fma2(acc[i][j], ap[i], bd[j]);
        }
        __syncthreads();
    }

    float v[8][8];
#pragma unroll
    for (int i = 0; i < 4; i++)
#pragma unroll
        for (int j = 0; j < 8; j++)
            up2(v[2 * i][j], v[2 * i + 1][j], acc[i][j]);
    float bv[8];
    *(float4*)&bv[0] = *(const float4*)&bc1[tx];
    *(float4*)&bv[4] = *(const float4*)&bc1[tx + 4];
#pragma unroll
    for (int j = 0; j < 8; j++) {
        float* q = ct + (tx + j) * 68 + ty;
        *(float4*)(q)     = make_float4(fmaxf(v[0][j]+bv[j],0.f), fmaxf(v[1][j]+bv[j],0.f),
                                        fmaxf(v[2][j]+bv[j],0.f), fmaxf(v[3][j]+bv[j],0.f));
        *(float4*)(q + 4) = make_float4(fmaxf(v[4][j]+bv[j],0.f), fmaxf(v[5][j]+bv[j],0.f),
                                        fmaxf(v[6][j]+bv[j],0.f), fmaxf(v[7][j]+bv[j],0.f));
    }
    __syncthreads();

    {
        const int r = tid >> 2;
        const int c = (tid & 3) * 2;
        float f0 = bc2[c], f1 = bc2[c + 1];
#pragma unroll 8
        for (int k = 0; k < 256; k++) {
            float a = ct[k * 68 + r];
            f0 += a * wc2[k * 8 + c];
            f1 += a * wc2[k * 8 + c + 1];
        }
        float* q = out + (bm + r) * 8 + c;
        q[0] = f0; q[1] = f1;
    }
}

// ---------------------------------------------------------------------------
// Launch: FF-edge(0), FF-node(1), LSTM(2), classifier(3 = profiled slot).
// ---------------------------------------------------------------------------
extern "C" void kernel_launch(void* const* d_in, const int* in_sizes, int n_in,
                              void* d_out, int out_size)
{
    const float* x_seq = (const float*)d_in[0];
    const float* ea    = (const float*)d_in[1];
    const float* Wn1   = (const float*)d_in[2];
    const float* bn1   = (const float*)d_in[3];
    const float* Wn2   = (const float*)d_in[4];
    const float* bn2   = (const float*)d_in[5];
    const float* We1   = (const float*)d_in[6];
    const float* be1   = (const float*)d_in[7];
    const float* We2   = (const float*)d_in[8];
    const float* be2   = (const float*)d_in[9];
    const float* Wg1   = (const float*)d_in[10];
    const float* bg1   = (const float*)d_in[11];
    const float* Wg2   = (const float*)d_in[12];
    const float* bg2   = (const float*)d_in[13];
    const float* Wef1  = (const float*)d_in[14];
    const float* bef1  = (const float*)d_in[15];
    const float* Wef2  = (const float*)d_in[16];
    const float* bef2  = (const float*)d_in[17];
    const float* Wih_n = (const float*)d_in[18];
    const float* Whh_n = (const float*)d_in[19];
    const float* b_n   = (const float*)d_in[20];
    const float* Wih_e = (const float*)d_in[21];
    const float* Whh_e = (const float*)d_in[22];
    const float* b_e   = (const float*)d_in[23];
    const float* Wc1   = (const float*)d_in[24];
    const float* bc1   = (const float*)d_in[25];
    const float* Wc2   = (const float*)d_in[26];
    const float* bc2   = (const float*)d_in[27];
    float* out = (float*)d_out;

    (void)in_sizes; (void)n_in; (void)out_size;

    const int SMF   = (128 * 128 * 2 + 128 * 132) * 4;
    const int SMC1F = (2048 + 16*68 + 16*256 + 256*68 + 256*8) * 4;
    cudaFuncSetAttribute(fused_ff<8, 0>,  cudaFuncAttributeMaxDynamicSharedMemorySize, SMF);
    cudaFuncSetAttribute(fused_ff<16, 1>, cudaFuncAttributeMaxDynamicSharedMemorySize, SMF);
    cudaFuncSetAttribute(lstm7,   cudaFuncAttributeMaxDynamicSharedMemorySize, LSTM7_SMEM_BYTES);
    cudaFuncSetAttribute(c1final, cudaFuncAttributeMaxDynamicSharedMemorySize, SMC1F);

    __half* e4 = (__half*)(g_arena + OFF_E4);
    __half* x4 = (__half*)(g_arena + OFF_X4);
    __half* hn = (__half*)(g_arena + OFF_HN);
    __half* he = (__half*)(g_arena + OFF_HE);

    // idx0: edge FF path ea -> e4 (fp16)
    fused_ff<8, 0><<<2048, 256, SMF>>>(ea,
        We1, be1, We2, be2, Wef1, bef1, Wef2, bef2, e4);
    // idx1: node FF path x_seq -> x4 (fp16, graph-conv mixes fused)
    fused_ff<16, 1><<<512, 256, SMF>>>(x_seq,
        Wn1, bn1, Wn2, bn2, Wg1, bg1, Wg2, bg2, x4);
    // idx2: fused LSTM v7 (best measured)
    lstm7<<<129, 512, LSTM7_SMEM_BYTES>>>(x4, Wih_n, Whh_n, b_n, hn,
                                          e4, Wih_e, Whh_e, b_e, he);
    // idx3: classifier v4 (reg-prefetch double buffering) [profiled]
    c1final<<<4096, 256, SMC1F>>>(hn, he, Wc1, bc1, Wc2, bc2, out);
}